// round 10
// baseline (speedup 1.0000x reference)
#include <cuda_runtime.h>

// Problem constants
#define T_STEPS 256
#define I1 38
#define H1 50
#define H2 15
#define NC 14
#define K1 (I1 + H1)    // 88
#define K2 (H1 + H2)    // 65
#define BT 28           // batches per block; grid 147 -> 1 block per SM
#define BTOT 4096
#define AST 28          // activation row stride (floats); 112B rows
#define NTHREADS 960
#define NBLOCKS 147

// Shared layout (floats):
//  W1s [K1][H1][4]  17600   (k, unit, gate i/f/g/o) -> 2 gate-pair u64 per (k,u)
//  W2s [K2][H2][4]   3900
//  b1v [H1][4]        200
//  b2v [H2][4]         60
//  wfcs[NC*H2]        210
//  bfcs[NC]            14
//  a1  [2][K1][AST]  4928   rows 0..I1-1 = x_t, rows I1.. = h1
//  a2  [2][H2][AST]   840   h2 only
#define OFF_W1   0
#define OFF_W2   (OFF_W1 + K1 * H1 * 4)
#define OFF_B1   (OFF_W2 + K2 * H2 * 4)
#define OFF_B2   (OFF_B1 + H1 * 4)
#define OFF_WFC  (OFF_B2 + H2 * 4)
#define OFF_BFC  (OFF_WFC + NC * H2)
#define OFF_A1   (OFF_BFC + NC)
#define OFF_A2   (OFF_A1 + 2 * K1 * AST)
#define SMEM_FLOATS (OFF_A2 + 2 * H2 * AST)
#define SMEM_BYTES (SMEM_FLOATS * 4)   // ~111 KB; 1 block/SM

__device__ __forceinline__ float fsig(float x) {
    return __fdividef(1.0f, 1.0f + __expf(-x));
}
__device__ __forceinline__ float ftanh_fast(float x) {
    return 1.0f - __fdividef(2.0f, 1.0f + __expf(2.0f * x));
}

__device__ __forceinline__ unsigned long long pack2(float w) {
    unsigned long long r;
    asm("mov.b64 %0, {%1, %1};" : "=l"(r) : "f"(w));
    return r;
}
__device__ __forceinline__ unsigned long long packf2(float a, float b) {
    unsigned long long r;
    asm("mov.b64 %0, {%1, %2};" : "=l"(r) : "f"(a), "f"(b));
    return r;
}
__device__ __forceinline__ void ffma2(unsigned long long& d,
                                      unsigned long long a, unsigned long long b) {
    asm("fma.rn.f32x2 %0, %1, %2, %0;" : "+l"(d) : "l"(a), "l"(b));
}
__device__ __forceinline__ float2 unpk2(unsigned long long v) {
    float2 r;
    asm("mov.b64 {%0, %1}, %2;" : "=f"(r.x), "=f"(r.y) : "l"(v));
    return r;
}

extern __shared__ float smem[];

__global__ __launch_bounds__(NTHREADS, 1)
void lstm2_fused_kernel(const float* __restrict__ x,
                        const float* __restrict__ w_ih1, const float* __restrict__ w_hh1,
                        const float* __restrict__ b_ih1, const float* __restrict__ b_hh1,
                        const float* __restrict__ w_ih2, const float* __restrict__ w_hh2,
                        const float* __restrict__ b_ih2, const float* __restrict__ b_hh2,
                        const float* __restrict__ w_fc, const float* __restrict__ b_fc,
                        float* __restrict__ out)
{
    float* W1s  = smem + OFF_W1;
    float* W2s  = smem + OFF_W2;
    float* b1v  = smem + OFF_B1;
    float* b2v  = smem + OFF_B2;
    float* wfcs = smem + OFF_WFC;
    float* bfcs = smem + OFF_BFC;
    float* a1   = smem + OFF_A1;
    float* a2   = smem + OFF_A2;

    const int tid = threadIdx.x;
    const int b0  = blockIdx.x * BT;

    // ---- stage weights: (k, unit, gate) float4 = (i,f) u64 + (g,o) u64 ----
    for (int i = tid; i < K1 * H1 * 4; i += NTHREADS) {
        int k = i / (H1 * 4);
        int r = i - k * (H1 * 4);
        int uu = r >> 2, gi = r & 3;
        W1s[i] = (k < I1) ? w_ih1[(gi * H1 + uu) * I1 + k]
                          : w_hh1[(gi * H1 + uu) * H1 + (k - I1)];
    }
    for (int i = tid; i < K2 * H2 * 4; i += NTHREADS) {
        int k = i / (H2 * 4);
        int r = i - k * (H2 * 4);
        int uu = r >> 2, gi = r & 3;
        W2s[i] = (k < H1) ? w_ih2[(gi * H2 + uu) * H1 + k]
                          : w_hh2[(gi * H2 + uu) * H2 + (k - H1)];
    }
    for (int i = tid; i < H1 * 4; i += NTHREADS) {
        int uu = i >> 2, gi = i & 3;
        b1v[i] = b_ih1[gi * H1 + uu] + b_hh1[gi * H1 + uu];
    }
    for (int i = tid; i < H2 * 4; i += NTHREADS) {
        int uu = i >> 2, gi = i & 3;
        b2v[i] = b_ih2[gi * H2 + uu] + b_hh2[gi * H2 + uu];
    }
    for (int i = tid; i < NC * H2; i += NTHREADS) wfcs[i] = w_fc[i];
    for (int i = tid; i < NC; i += NTHREADS) bfcs[i] = b_fc[i];

    // ---- zero initial states (buffer 0); load x_0 (batch-clamped) ----
    for (int i = tid; i < H1 * AST; i += NTHREADS) a1[I1 * AST + i] = 0.0f;
    for (int i = tid; i < H2 * AST; i += NTHREADS) a2[i] = 0.0f;
    for (int i = tid; i < BT * I1; i += NTHREADS) {
        int b = i / I1, k = i % I1;
        int bg = b0 + b; if (bg > BTOT - 1) bg = BTOT - 1;
        a1[k * AST + b] = x[(size_t)bg * (T_STEPS * I1) + k];
    }

    // ---- thread roles ----
    // Phase 1: warps 0..24. Warp = 2 units; half-warp = 1 unit; lane hp = batch-pair.
    const int w_id = tid >> 5;
    const int lane = tid & 31;
    const bool is_p1 = (w_id < 25);
    const int half = lane >> 4;                 // 0/1 -> unit select
    const int hp_raw = lane & 15;               // 0..15
    const bool hp_on = hp_raw < (BT / 2);       // 14 active pairs
    const int hp = hp_on ? hp_raw : (BT / 2 - 1);
    const int u = 2 * w_id + half;              // 0..49

    // Phase 2: tids 800..904 (105): u2 = j/7 (0..14), quad = j%7 (0..6), 4 batches
    const bool is_p2 = (tid >= 800) && (tid < 905);
    const int j2 = tid - 800;
    const int u2 = j2 / 7;
    const int qd = j2 % 7;

    // Prefetch: warp 29 (tids 928..959): lane j = one batch, 38 floats/step
    const bool is_pf = (tid >= 928) && (tid < 928 + BT);
    int bg_pf = 0;
    if (is_pf) {
        bg_pf = b0 + (tid - 928); if (bg_pf > BTOT - 1) bg_pf = BTOT - 1;
    }

    float c1r[2] = {0.f, 0.f};
    float c2r[4] = {0.f, 0.f, 0.f, 0.f};

    __syncthreads();

    const ulonglong2* W1p = reinterpret_cast<const ulonglong2*>(W1s);
    const ulonglong2* W2p = reinterpret_cast<const ulonglong2*>(W2s);

    for (int t = 0; t < T_STEPS; ++t) {
        const int p = t & 1, q = p ^ 1;
        float* a1p = a1 + p * (K1 * AST);
        float* a1q = a1 + q * (K1 * AST);
        float* a2p = a2 + p * (H2 * AST);
        float* a2q = a2 + q * (H2 * AST);

        // ===== Phase 1: 800 threads; 1 unit x 4 gates x 2 batches per lane =====
        if (is_p1) {
            ulonglong2 bv = *reinterpret_cast<const ulonglong2*>(b1v + u * 4);
            unsigned long long aif0 = bv.x, ago0 = bv.y;   // batch 2hp
            unsigned long long aif1 = bv.x, ago1 = bv.y;   // batch 2hp+1
            const ulonglong2* wp = W1p + u;
            const float* ap = a1p + 2 * hp;
            #pragma unroll 8
            for (int k = 0; k < K1; ++k) {
                ulonglong2 wv = *wp; wp += H1;                 // broadcast in half-warp
                unsigned long long av =
                    *reinterpret_cast<const unsigned long long*>(ap); ap += AST;
                float2 af = unpk2(av);
                unsigned long long A0 = pack2(af.x);
                unsigned long long A1 = pack2(af.y);
                ffma2(aif0, wv.x, A0); ffma2(ago0, wv.y, A0);
                ffma2(aif1, wv.x, A1); ffma2(ago1, wv.y, A1);
            }
            float2 vif0 = unpk2(aif0), vgo0 = unpk2(ago0);
            float2 vif1 = unpk2(aif1), vgo1 = unpk2(ago1);
            float h0, h1;
            {
                float ig = fsig(vif0.x), fg = fsig(vif0.y);
                float gg = ftanh_fast(vgo0.x), og = fsig(vgo0.y);
                float c = fg * c1r[0] + ig * gg; c1r[0] = c;
                h0 = og * ftanh_fast(c);
            }
            {
                float ig = fsig(vif1.x), fg = fsig(vif1.y);
                float gg = ftanh_fast(vgo1.x), og = fsig(vgo1.y);
                float c = fg * c1r[1] + ig * gg; c1r[1] = c;
                h1 = og * ftanh_fast(c);
            }
            if (hp_on) {
                *reinterpret_cast<unsigned long long*>(
                    a1q + (I1 + u) * AST + 2 * hp) = packf2(h0, h1);
            }
        } else if (is_pf) {
            // prefetch x_{t+1}: one batch per lane, 38 consecutive floats
            if (t + 1 < T_STEPS) {
                const float* xr = x + (size_t)bg_pf * (T_STEPS * I1)
                                    + (size_t)(t + 1) * I1;
                float* dst = a1q + (tid - 928);
                #pragma unroll
                for (int k = 0; k < I1; ++k) dst[k * AST] = xr[k];
            }
        }

        __syncthreads();   // the ONLY barrier per step

        // ===== Phase 2: 105 threads; 1 unit x 4 gates x 4 batches =====
        // reads h1 from a1q h-rows (this step), h2 from a2p (prev step)
        if (is_p2) {
            ulonglong2 bv2 = *reinterpret_cast<const ulonglong2*>(b2v + u2 * 4);
            unsigned long long aif[4], ago[4];
            #pragma unroll
            for (int b = 0; b < 4; ++b) { aif[b] = bv2.x; ago[b] = bv2.y; }

            const ulonglong2* wp2 = W2p + u2;
            const float* ah = a1q + I1 * AST + 4 * qd;      // h1 (new)
            #pragma unroll 5
            for (int k = 0; k < H1; ++k) {
                ulonglong2 wv = *wp2; wp2 += H2;
                float4 af = *reinterpret_cast<const float4*>(ah); ah += AST;
                unsigned long long A0 = pack2(af.x);
                unsigned long long A1 = pack2(af.y);
                unsigned long long A2 = pack2(af.z);
                unsigned long long A3 = pack2(af.w);
                ffma2(aif[0], wv.x, A0); ffma2(ago[0], wv.y, A0);
                ffma2(aif[1], wv.x, A1); ffma2(ago[1], wv.y, A1);
                ffma2(aif[2], wv.x, A2); ffma2(ago[2], wv.y, A2);
                ffma2(aif[3], wv.x, A3); ffma2(ago[3], wv.y, A3);
            }
            const float* ah2 = a2p + 4 * qd;                // h2 (old)
            #pragma unroll
            for (int k = 0; k < H2; ++k) {
                ulonglong2 wv = *wp2; wp2 += H2;
                float4 af = *reinterpret_cast<const float4*>(ah2); ah2 += AST;
                unsigned long long A0 = pack2(af.x);
                unsigned long long A1 = pack2(af.y);
                unsigned long long A2 = pack2(af.z);
                unsigned long long A3 = pack2(af.w);
                ffma2(aif[0], wv.x, A0); ffma2(ago[0], wv.y, A0);
                ffma2(aif[1], wv.x, A1); ffma2(ago[1], wv.y, A1);
                ffma2(aif[2], wv.x, A2); ffma2(ago[2], wv.y, A2);
                ffma2(aif[3], wv.x, A3); ffma2(ago[3], wv.y, A3);
            }
            float hv[4];
            #pragma unroll
            for (int b = 0; b < 4; ++b) {
                float2 vif = unpk2(aif[b]);
                float2 vgo = unpk2(ago[b]);
                float ig = fsig(vif.x), fg = fsig(vif.y);
                float gg = ftanh_fast(vgo.x), og = fsig(vgo.y);
                float c = fg * c2r[b] + ig * gg; c2r[b] = c;
                hv[b] = og * ftanh_fast(c);
            }
            *reinterpret_cast<float4*>(a2q + u2 * AST + 4 * qd) =
                make_float4(hv[0], hv[1], hv[2], hv[3]);
        }
        // no barrier: next phase-1 touches disjoint rows/buffers
    }

    __syncthreads();
    // final h2 in buffer q of step 255: q = 0
    if (tid < BT * NC) {
        int b = tid / NC, n = tid % NC;
        int bg = b0 + b;
        if (bg < BTOT) {
            const float* h2f = a2;   // buffer 0
            float s = bfcs[n];
            #pragma unroll
            for (int j = 0; j < H2; ++j)
                s += h2f[j * AST + b] * wfcs[n * H2 + j];
            out[(size_t)bg * NC + n] = s;
        }
    }
}

extern "C" void kernel_launch(void* const* d_in, const int* in_sizes, int n_in,
                              void* d_out, int out_size)
{
    (void)in_sizes; (void)n_in; (void)out_size;
    const float* x     = (const float*)d_in[0];
    const float* w_ih1 = (const float*)d_in[1];
    const float* w_hh1 = (const float*)d_in[2];
    const float* b_ih1 = (const float*)d_in[3];
    const float* b_hh1 = (const float*)d_in[4];
    const float* w_ih2 = (const float*)d_in[5];
    const float* w_hh2 = (const float*)d_in[6];
    const float* b_ih2 = (const float*)d_in[7];
    const float* b_hh2 = (const float*)d_in[8];
    const float* w_fc  = (const float*)d_in[9];
    const float* b_fc  = (const float*)d_in[10];
    float* out = (float*)d_out;

    cudaFuncSetAttribute(lstm2_fused_kernel,
                         cudaFuncAttributeMaxDynamicSharedMemorySize, SMEM_BYTES);

    lstm2_fused_kernel<<<NBLOCKS, NTHREADS, SMEM_BYTES>>>(
        x, w_ih1, w_hh1, b_ih1, b_hh1,
        w_ih2, w_hh2, b_ih2, b_hh2,
        w_fc, b_fc, out);
}